// round 7
// baseline (speedup 1.0000x reference)
#include <cuda_runtime.h>
#include <cuda_bf16.h>
#include <cstdint>
#include <math.h>

// out = GELU_exact(x @ W.T + b)
// Split-precision bf16 mma.sync GEMM: acc += Ahi*Bhi + Ahi*Blo + Alo*Bhi (fp32 accum).
// R7: warp phase skew (odd warps run k-slices in reverse order) so LDSM bursts of
// half the warps overlap MMA bursts of the other half; compile-time KS bodies to
// fold swizzle address math.

#define NN 8192
#define KK 512
#define OO 512

#define BM 128
#define BN 128
#define BK 32
#define NKT (KK / BK)          // 16
#define THREADS 512

// stage layout (bytes): Ahi[128x32] 8K | Alo 8K | Bhi 8K | Blo 8K
#define ST_ALO  8192
#define ST_BHI  16384
#define ST_BLO  24576
#define STAGE   32768
#define NSTAGE  3
#define SMEM_TOTAL (NSTAGE * STAGE)   // 96 KB

// unified packed scratch: [xhi | xlo | whi | wlo]
#define OFF_XHI 0
#define OFF_XLO (NN * KK)
#define OFF_WHI (2 * NN * KK)
#define OFF_WLO (2 * NN * KK + OO * KK)
__device__ __align__(128) __nv_bfloat16 g_pack[2 * NN * KK + 2 * OO * KK];

__device__ __forceinline__ uint32_t smem_u32(const void* p) {
    uint32_t a;
    asm("{ .reg .u64 t; cvta.to.shared.u64 t, %1; cvt.u32.u64 %0, t; }" : "=r"(a) : "l"(p));
    return a;
}

#define CP16(dst, src) \
    asm volatile("cp.async.cg.shared.global [%0], [%1], 16;" :: "r"(dst), "l"(src) : "memory")
#define CP_COMMIT() asm volatile("cp.async.commit_group;" ::: "memory")
#define CP_WAIT1()  asm volatile("cp.async.wait_group 1;" ::: "memory")

__device__ __forceinline__ void ldm4(uint32_t* r, uint32_t addr) {
    asm volatile("ldmatrix.sync.aligned.m8n8.x4.shared.b16 {%0,%1,%2,%3}, [%4];"
                 : "=r"(r[0]), "=r"(r[1]), "=r"(r[2]), "=r"(r[3]) : "r"(addr));
}

__device__ __forceinline__ void mma_bf16(float* d, const uint32_t* a, const uint32_t* b) {
    asm volatile(
        "mma.sync.aligned.m16n8k16.row.col.f32.bf16.bf16.f32 "
        "{%0,%1,%2,%3}, {%4,%5,%6,%7}, {%8,%9}, {%0,%1,%2,%3};"
        : "+f"(d[0]), "+f"(d[1]), "+f"(d[2]), "+f"(d[3])
        : "r"(a[0]), "r"(a[1]), "r"(a[2]), "r"(a[3]), "r"(b[0]), "r"(b[1]));
}

// swizzled byte offset inside a tile: row r (64B rows = 4 x 16B chunks), chunk c
__device__ __forceinline__ uint32_t swz(int r, int c) {
    return (uint32_t)(r * 64 + ((c ^ ((r >> 1) & 3)) << 4));
}

// A&S 7.1.26 erf (abs err 1.5e-7)
__device__ __forceinline__ float gelu_f(float h) {
    float s = h * 0.70710678118654752f;
    float a = fabsf(s);
    float t = __frcp_rn(fmaf(0.3275911f, a, 1.0f));
    float p = fmaf(fmaf(fmaf(fmaf(1.061405429f, t, -1.453152027f), t, 1.421413741f),
                        t, -0.284496736f), t, 0.254829592f) * t;
    float e = __expf(-a * a);
    float erfv = fmaf(-p, e, 1.0f);
    erfv = copysignf(erfv, s);
    return 0.5f * h * (1.0f + erfv);
}

// ---------------- pack kernel: f32 -> bf16 hi/lo ----------------
__global__ __launch_bounds__(256) void pack_kernel(const float* __restrict__ x,
                                                   const float* __restrict__ W) {
    const int g = blockIdx.x * 256 + threadIdx.x;
    const int A_GROUPS = NN * (KK / 8);   // 524288
    const float* src;
    __nv_bfloat16 *dhi, *dlo;
    if (g < A_GROUPS) {
        src = x + (size_t)g * 8;
        dhi = g_pack + OFF_XHI + (size_t)g * 8;
        dlo = g_pack + OFF_XLO + (size_t)g * 8;
    } else {
        size_t g2 = (size_t)(g - A_GROUPS);
        src = W + g2 * 8;
        dhi = g_pack + OFF_WHI + g2 * 8;
        dlo = g_pack + OFF_WLO + g2 * 8;
    }
    float4 v0 = *(const float4*)src;
    float4 v1 = *(const float4*)(src + 4);
    float f[8] = {v0.x, v0.y, v0.z, v0.w, v1.x, v1.y, v1.z, v1.w};
    uint32_t hi[4], lo[4];
#pragma unroll
    for (int j = 0; j < 4; j++) {
        __nv_bfloat16 h0 = __float2bfloat16(f[2 * j]);
        __nv_bfloat16 h1 = __float2bfloat16(f[2 * j + 1]);
        __nv_bfloat16 l0 = __float2bfloat16(f[2 * j] - __bfloat162float(h0));
        __nv_bfloat16 l1 = __float2bfloat16(f[2 * j + 1] - __bfloat162float(h1));
        hi[j] = (uint32_t)__bfloat16_as_ushort(h0) | ((uint32_t)__bfloat16_as_ushort(h1) << 16);
        lo[j] = (uint32_t)__bfloat16_as_ushort(l0) | ((uint32_t)__bfloat16_as_ushort(l1) << 16);
    }
    *(uint4*)dhi = make_uint4(hi[0], hi[1], hi[2], hi[3]);
    *(uint4*)dlo = make_uint4(lo[0], lo[1], lo[2], lo[3]);
}

// ---------------- main GEMM kernel ----------------
__device__ __forceinline__ void load_stage(uint32_t S, int buf, int kt, int mb, int nb, int tid) {
    const uint32_t st = S + buf * STAGE;
    const int kbase = kt * BK;
    const int r = tid >> 2, c = tid & 3;
    const uint32_t sw = swz(r, c);
    {
        size_t so = (size_t)(mb * BM + r) * KK + kbase + c * 8;
        CP16(st + sw, (const uint8_t*)(g_pack + OFF_XHI + so));
        CP16(st + ST_ALO + sw, (const uint8_t*)(g_pack + OFF_XLO + so));
    }
    {
        size_t so = (size_t)(nb * BN + r) * KK + kbase + c * 8;
        CP16(st + ST_BHI + sw, (const uint8_t*)(g_pack + OFF_WHI + so));
        CP16(st + ST_BLO + sw, (const uint8_t*)(g_pack + OFF_WLO + so));
    }
    CP_COMMIT();
}

// one k-slice of compute, KS compile-time so all swizzle offsets fold
template <int KS>
__device__ __forceinline__ void ks_body(uint32_t stg, float acc[2][4][4],
                                        int mwarp, int nwarp,
                                        int a_r, int a_cs, int b_n, int b_cs) {
    const int c0 = KS * 2;
    uint32_t Bh[8], Ah[8], T[8];
#pragma unroll
    for (int nf2 = 0; nf2 < 2; nf2++)
        ldm4(&Bh[nf2 * 4], stg + ST_BHI + swz(nwarp * 32 + nf2 * 16 + b_n, c0 + b_cs));
#pragma unroll
    for (int mf = 0; mf < 2; mf++)
        ldm4(&Ah[mf * 4], stg + swz(mwarp * 32 + mf * 16 + a_r, c0 + a_cs));
    // hh
#pragma unroll
    for (int mf = 0; mf < 2; mf++)
#pragma unroll
        for (int nf = 0; nf < 4; nf++)
            mma_bf16(acc[mf][nf], &Ah[mf * 4], &Bh[nf * 2]);
    // T = A lo ; lh
#pragma unroll
    for (int mf = 0; mf < 2; mf++)
        ldm4(&T[mf * 4], stg + ST_ALO + swz(mwarp * 32 + mf * 16 + a_r, c0 + a_cs));
#pragma unroll
    for (int mf = 0; mf < 2; mf++)
#pragma unroll
        for (int nf = 0; nf < 4; nf++)
            mma_bf16(acc[mf][nf], &T[mf * 4], &Bh[nf * 2]);
    // T = B lo ; hl
#pragma unroll
    for (int nf2 = 0; nf2 < 2; nf2++)
        ldm4(&T[nf2 * 4], stg + ST_BLO + swz(nwarp * 32 + nf2 * 16 + b_n, c0 + b_cs));
#pragma unroll
    for (int mf = 0; mf < 2; mf++)
#pragma unroll
        for (int nf = 0; nf < 4; nf++)
            mma_bf16(acc[mf][nf], &Ah[mf * 4], &T[nf * 2]);
}

__global__ __launch_bounds__(THREADS, 2)
void gemm_mma_kernel(const float* __restrict__ bias, float* __restrict__ C) {
    extern __shared__ uint8_t smem[];
    const uint32_t S = smem_u32(smem);
    const int tid = threadIdx.x;
    const int l = tid & 31, wid = tid >> 5;
    const int mwarp = wid & 3;   // 4 M-warps of 32 rows
    const int nwarp = wid >> 2;  // 4 N-warps of 32 cols
    const int skew = wid & 1;    // phase skew: odd warps do ks {1,0}
    const int mb = blockIdx.x, nb = blockIdx.y;

    const int a_r = ((l >> 3) & 1) * 8 + (l & 7);
    const int a_cs = (l >> 4) & 1;
    const int b_n = ((l >> 4) & 1) * 8 + (l & 7);
    const int b_cs = (l >> 3) & 1;

    float acc[2][4][4];
#pragma unroll
    for (int i = 0; i < 2; i++)
#pragma unroll
        for (int j = 0; j < 4; j++)
#pragma unroll
            for (int k = 0; k < 4; k++) acc[i][j][k] = 0.0f;

    load_stage(S, 0, 0, mb, nb, tid);
    load_stage(S, 1, 1, mb, nb, tid);

    for (int kt = 0; kt < NKT; kt++) {
        CP_WAIT1();
        __syncthreads();
        if (kt + 2 < NKT) load_stage(S, (kt + 2) % NSTAGE, kt + 2, mb, nb, tid);
        const uint32_t stg = S + (kt % NSTAGE) * STAGE;

        if (skew) {
            ks_body<1>(stg, acc, mwarp, nwarp, a_r, a_cs, b_n, b_cs);
            ks_body<0>(stg, acc, mwarp, nwarp, a_r, a_cs, b_n, b_cs);
        } else {
            ks_body<0>(stg, acc, mwarp, nwarp, a_r, a_cs, b_n, b_cs);
            ks_body<1>(stg, acc, mwarp, nwarp, a_r, a_cs, b_n, b_cs);
        }
    }

    // epilogue: bias + GELU
#pragma unroll
    for (int mf = 0; mf < 2; mf++) {
#pragma unroll
        for (int nf = 0; nf < 4; nf++) {
            int m0 = mb * BM + mwarp * 32 + mf * 16 + (l >> 2);
            int n0 = nb * BN + nwarp * 32 + nf * 8 + 2 * (l & 3);
            float b0 = __ldg(&bias[n0]);
            float b1 = __ldg(&bias[n0 + 1]);
            float2 v0, v1;
            v0.x = gelu_f(acc[mf][nf][0] + b0);
            v0.y = gelu_f(acc[mf][nf][1] + b1);
            v1.x = gelu_f(acc[mf][nf][2] + b0);
            v1.y = gelu_f(acc[mf][nf][3] + b1);
            *(float2*)&C[(size_t)m0 * OO + n0] = v0;
            *(float2*)&C[(size_t)(m0 + 8) * OO + n0] = v1;
        }
    }
}

// ---------------- launch ----------------
extern "C" void kernel_launch(void* const* d_in, const int* in_sizes, int n_in,
                              void* d_out, int out_size) {
    const float* x = (const float*)d_in[0];
    const float* W = (const float*)d_in[2];
    const float* b = (const float*)d_in[3];
    float* out = (float*)d_out;

    cudaFuncSetAttribute(gemm_mma_kernel,
                         cudaFuncAttributeMaxDynamicSharedMemorySize, SMEM_TOTAL);

    const int A_GROUPS = NN * (KK / 8);
    const int B_GROUPS = OO * (KK / 8);
    pack_kernel<<<(A_GROUPS + B_GROUPS) / 256, 256>>>(x, W);

    dim3 grid(NN / BM, OO / BN);  // (64, 4) = 256 CTAs, 2/SM, single wave
    gemm_mma_kernel<<<grid, THREADS, SMEM_TOTAL>>>(b, out);
}